// round 9
// baseline (speedup 1.0000x reference)
#include <cuda_runtime.h>

#define BB 128
#define SS 512
#define CC 128
#define NTHREADS 128

__device__ float g_partial[BB];

__device__ __forceinline__ unsigned long long fma2(unsigned long long a,
                                                   unsigned long long b,
                                                   unsigned long long c) {
    unsigned long long d;
    asm("fma.rn.f32x2 %0, %1, %2, %3;" : "=l"(d) : "l"(a), "l"(b), "l"(c));
    return d;
}
__device__ __forceinline__ unsigned long long pack2(float x, float y) {
    unsigned long long v;
    asm("mov.b64 %0, {%1, %2};" : "=l"(v) : "f"(x), "f"(y));
    return v;
}
__device__ __forceinline__ void unpack2(unsigned long long v, float& x, float& y) {
    asm("mov.b64 {%0, %1}, %2;" : "=f"(x), "=f"(y) : "l"(v));
}

__global__ __launch_bounds__(NTHREADS, 1)
void crf_main_kernel(const float* __restrict__ em,          // [B,S,C] f32
                     const int* __restrict__ tags32,        // int32 or int64 (detected)
                     const unsigned char* __restrict__ mask,// [B,S] elem width detected
                     const float* __restrict__ trans,       // [C,C] f32
                     const float* __restrict__ start_t,     // [C]
                     const float* __restrict__ end_t)       // [C]
{
    const int b   = blockIdx.x;
    const int j   = threadIdx.x;
    const int wid = j >> 5;
    const int lid = j & 31;

    __shared__ __align__(16) float lin[2][CC];
    __shared__ float red[16];
    __shared__ float s_gold;

    const float* emB = em + (size_t)b * SS * CC;

    // ---- detect tags element width: int64 => odd 32-bit words all zero ----
    int oddw = (j < 64) ? tags32[2 * j + 1] : 0;
    int any_odd = __syncthreads_or(oddw != 0);
    const int tstride = (any_odd == 0) ? 2 : 1;              // words per tag
    const int* tagB = tags32 + (size_t)b * SS * tstride;

    // ---- detect mask element width by probing first 64 words ----
    // 1-byte bools (value 0/1): words look like 0x01010101 (> 1 somewhere)
    // 4-byte ints : words are 0/1 at every index
    // 8-byte ints : words are 0/1 at even indices, 0 at odd indices
    const unsigned* mw = (const unsigned*)mask;
    unsigned w = (j < 64) ? mw[j] : 0u;
    int any_gt1     = __syncthreads_or((int)(w > 1u));
    int any_odd_nz  = __syncthreads_or((int)((j & 1) && j < 64 && w != 0u));
    const int mstride = any_gt1 ? 1 : (any_odd_nz ? 4 : 8);
    const unsigned char* mkB = mask + (size_t)b * SS * mstride;

    // ---- gold score (cooperative gathers) ----
    float lg = 0.f;
    int   mc = 0;
    for (int t = j; t < SS; t += NTHREADS) {
        int tag = tagB[t * tstride];
        unsigned char m = mkB[t * mstride];
        mc += m ? 1 : 0;
        if (t == 0) {
            lg += start_t[tag] + emB[tag];
        } else if (m) {
            int pt = tagB[(t - 1) * tstride];
            lg += emB[t * CC + tag] + trans[pt * CC + tag];
        }
    }
    #pragma unroll
    for (int o = 16; o; o >>= 1) {
        lg += __shfl_xor_sync(0xffffffffu, lg, o);
        mc += __shfl_xor_sync(0xffffffffu, mc, o);
    }
    if (lid == 0) { red[wid] = lg; red[8 + wid] = (float)mc; }
    __syncthreads();
    if (j == 0) {
        float g = red[0] + red[1] + red[2] + red[3];
        int mct = (int)(red[8] + red[9] + red[10] + red[11]);
        int last = mct - 1;
        if (last < 0) last = 0;
        int ltag = tagB[last * tstride];
        s_gold = g + end_t[ltag];
    }

    // ---- expT column j -> 64 packed f32x2 registers ----
    unsigned long long Ecol[64];
    #pragma unroll
    for (int k = 0; k < 64; k++) {
        float e0 = __expf(trans[(2 * k)     * CC + j]);
        float e1 = __expf(trans[(2 * k + 1) * CC + j]);
        Ecol[k] = pack2(e0, e1);
    }

    // ---- init alpha (linear space) ----
    float v = __expf(start_t[j] + emB[j]);
    lin[0][j] = v;
    float logscale = 0.f;
    __syncthreads();

    int cur = 0;

    // prefetch pipeline: emissions + mask for next 4 steps
    float         ebuf[4];
    unsigned char mbuf[4];
    #pragma unroll
    for (int k = 0; k < 4; k++) {
        int t = 1 + k;
        ebuf[k] = emB[t * CC + j];
        mbuf[k] = mkB[t * mstride];
    }

    for (int t0 = 1; t0 < SS; t0 += 4) {
        float         enext[4];
        unsigned char mnext[4];
        #pragma unroll
        for (int k = 0; k < 4; k++) {
            int t = t0 + 4 + k;
            if (t < SS) { enext[k] = emB[t * CC + j]; mnext[k] = mkB[t * mstride]; }
            else        { enext[k] = 0.f;             mnext[k] = 0; }
        }

        #pragma unroll
        for (int k = 0; k < 4; k++) {
            int t = t0 + k;
            bool active = (t < SS) && (mbuf[k] != 0);
            const unsigned long long* lp =
                (const unsigned long long*)lin[cur];
            unsigned long long a0 = 0ull, a1 = 0ull;
            #pragma unroll
            for (int q = 0; q < 64; q += 2) {
                a0 = fma2(lp[q],     Ecol[q],     a0);
                a1 = fma2(lp[q + 1], Ecol[q + 1], a1);
            }
            float x0, x1, y0, y1;
            unpack2(a0, x0, x1);
            unpack2(a1, y0, y1);
            float dot = (x0 + x1) + (y0 + y1);
            float nv = dot * __expf(ebuf[k]);
            v = active ? nv : v;
            lin[cur ^ 1][j] = v;
            cur ^= 1;
            __syncthreads();
        }

        // ---- renormalize by exact power of 2 (every 4 steps) ----
        float m = v;
        #pragma unroll
        for (int o = 16; o; o >>= 1)
            m = fmaxf(m, __shfl_xor_sync(0xffffffffu, m, o));
        if (lid == 0) red[wid] = m;
        __syncthreads();
        m = fmaxf(fmaxf(red[0], red[1]), fmaxf(red[2], red[3]));
        int e = (__float_as_int(m) >> 23) - 127;
        if (e != 0) {
            float scale = __int_as_float((127 - e) << 23); // 2^-e, exact
            v *= scale;
            lin[cur][j] = v;
            logscale += (float)e * 0.6931471805599453f;
        }
        __syncthreads();

        #pragma unroll
        for (int k = 0; k < 4; k++) { ebuf[k] = enext[k]; mbuf[k] = mnext[k]; }
    }

    // ---- finalize partition: log( sum_j lin[j]*exp(end_t[j]) ) + logscale ----
    float fv = v * __expf(end_t[j]);
    #pragma unroll
    for (int o = 16; o; o >>= 1)
        fv += __shfl_xor_sync(0xffffffffu, fv, o);
    if (lid == 0) red[wid] = fv;
    __syncthreads();
    if (j == 0) {
        float s = red[0] + red[1] + red[2] + red[3];
        float part = __logf(s) + logscale;
        g_partial[b] = part - s_gold;   // contribution to mean(part - gold)
    }
}

__global__ void crf_reduce_kernel(float* __restrict__ out) {
    const int j = threadIdx.x;
    __shared__ float r[4];
    float vv = g_partial[j];
    #pragma unroll
    for (int o = 16; o; o >>= 1)
        vv += __shfl_xor_sync(0xffffffffu, vv, o);
    if ((j & 31) == 0) r[j >> 5] = vv;
    __syncthreads();
    if (j == 0)
        out[0] = (r[0] + r[1] + r[2] + r[3]) * (1.0f / (float)BB);
}

extern "C" void kernel_launch(void* const* d_in, const int* in_sizes, int n_in,
                              void* d_out, int out_size) {
    const float*         em    = (const float*)d_in[0];
    const int*           tags  = (const int*)d_in[1];
    const unsigned char* mask  = (const unsigned char*)d_in[2];
    const float*         trans = (const float*)d_in[3];
    const float*         st    = (const float*)d_in[4];
    const float*         et    = (const float*)d_in[5];
    float* out = (float*)d_out;

    crf_main_kernel<<<BB, NTHREADS>>>(em, tags, mask, trans, st, et);
    crf_reduce_kernel<<<1, NTHREADS>>>(out);
}

// round 10
// speedup vs baseline: 1.0007x; 1.0007x over previous
#include <cuda_runtime.h>

#define BB 128
#define SS 512
#define CC 128
#define NTHREADS 128

__device__ float g_partial[BB];

__device__ __forceinline__ unsigned long long fma2(unsigned long long a,
                                                   unsigned long long b,
                                                   unsigned long long c) {
    unsigned long long d;
    asm("fma.rn.f32x2 %0, %1, %2, %3;" : "=l"(d) : "l"(a), "l"(b), "l"(c));
    return d;
}
__device__ __forceinline__ unsigned long long pack2(float x, float y) {
    unsigned long long v;
    asm("mov.b64 %0, {%1, %2};" : "=l"(v) : "f"(x), "f"(y));
    return v;
}
__device__ __forceinline__ void unpack2(unsigned long long v, float& x, float& y) {
    asm("mov.b64 {%0, %1}, %2;" : "=f"(x), "=f"(y) : "l"(v));
}

__global__ __launch_bounds__(NTHREADS, 1)
void crf_main_kernel(const float* __restrict__ em,          // [B,S,C] f32
                     const int* __restrict__ tags32,        // int32 or int64 (detected)
                     const unsigned char* __restrict__ mask,// [B,S] elem width detected
                     const float* __restrict__ trans,       // [C,C] f32
                     const float* __restrict__ start_t,     // [C]
                     const float* __restrict__ end_t)       // [C]
{
    const int b   = blockIdx.x;
    const int j   = threadIdx.x;
    const int wid = j >> 5;
    const int lid = j & 31;

    __shared__ __align__(16) float lin[2][CC];
    __shared__ float red[16];
    __shared__ float s_gold;

    const float* emB = em + (size_t)b * SS * CC;

    // ---- detect tags element width: int64 => odd 32-bit words all zero ----
    int oddw = (j < 64) ? tags32[2 * j + 1] : 0;
    int any_odd = __syncthreads_or(oddw != 0);
    const int tstride = (any_odd == 0) ? 2 : 1;              // words per tag
    const int* tagB = tags32 + (size_t)b * SS * tstride;

    // ---- detect mask element width by probing first 64 words ----
    // 1-byte bools (value 0/1): words look like 0x01010101 (> 1 somewhere)
    // 4-byte ints : words are 0/1 at every index
    // 8-byte ints : words are 0/1 at even indices, 0 at odd indices
    const unsigned* mw = (const unsigned*)mask;
    unsigned w = (j < 64) ? mw[j] : 0u;
    int any_gt1     = __syncthreads_or((int)(w > 1u));
    int any_odd_nz  = __syncthreads_or((int)((j & 1) && j < 64 && w != 0u));
    const int mstride = any_gt1 ? 1 : (any_odd_nz ? 4 : 8);
    const unsigned char* mkB = mask + (size_t)b * SS * mstride;

    // ---- gold score (cooperative gathers) ----
    float lg = 0.f;
    int   mc = 0;
    for (int t = j; t < SS; t += NTHREADS) {
        int tag = tagB[t * tstride];
        unsigned char m = mkB[t * mstride];
        mc += m ? 1 : 0;
        if (t == 0) {
            lg += start_t[tag] + emB[tag];
        } else if (m) {
            int pt = tagB[(t - 1) * tstride];
            lg += emB[t * CC + tag] + trans[pt * CC + tag];
        }
    }
    #pragma unroll
    for (int o = 16; o; o >>= 1) {
        lg += __shfl_xor_sync(0xffffffffu, lg, o);
        mc += __shfl_xor_sync(0xffffffffu, mc, o);
    }
    if (lid == 0) { red[wid] = lg; red[8 + wid] = (float)mc; }
    __syncthreads();
    if (j == 0) {
        float g = red[0] + red[1] + red[2] + red[3];
        int mct = (int)(red[8] + red[9] + red[10] + red[11]);
        int last = mct - 1;
        if (last < 0) last = 0;
        int ltag = tagB[last * tstride];
        s_gold = g + end_t[ltag];
    }

    // ---- expT column j -> 64 packed f32x2 registers ----
    unsigned long long Ecol[64];
    #pragma unroll
    for (int k = 0; k < 64; k++) {
        float e0 = __expf(trans[(2 * k)     * CC + j]);
        float e1 = __expf(trans[(2 * k + 1) * CC + j]);
        Ecol[k] = pack2(e0, e1);
    }

    // ---- init alpha (linear space) ----
    float v = __expf(start_t[j] + emB[j]);
    lin[0][j] = v;
    float logscale = 0.f;
    __syncthreads();

    int cur = 0;

    // prefetch pipeline: emissions + mask for next 4 steps
    float         ebuf[4];
    unsigned char mbuf[4];
    #pragma unroll
    for (int k = 0; k < 4; k++) {
        int t = 1 + k;
        ebuf[k] = emB[t * CC + j];
        mbuf[k] = mkB[t * mstride];
    }

    for (int t0 = 1; t0 < SS; t0 += 4) {
        float         enext[4];
        unsigned char mnext[4];
        #pragma unroll
        for (int k = 0; k < 4; k++) {
            int t = t0 + 4 + k;
            if (t < SS) { enext[k] = emB[t * CC + j]; mnext[k] = mkB[t * mstride]; }
            else        { enext[k] = 0.f;             mnext[k] = 0; }
        }

        #pragma unroll
        for (int k = 0; k < 4; k++) {
            int t = t0 + k;
            bool active = (t < SS) && (mbuf[k] != 0);
            const unsigned long long* lp =
                (const unsigned long long*)lin[cur];
            unsigned long long a0 = 0ull, a1 = 0ull;
            #pragma unroll
            for (int q = 0; q < 64; q += 2) {
                a0 = fma2(lp[q],     Ecol[q],     a0);
                a1 = fma2(lp[q + 1], Ecol[q + 1], a1);
            }
            float x0, x1, y0, y1;
            unpack2(a0, x0, x1);
            unpack2(a1, y0, y1);
            float dot = (x0 + x1) + (y0 + y1);
            float nv = dot * __expf(ebuf[k]);
            v = active ? nv : v;
            lin[cur ^ 1][j] = v;
            cur ^= 1;
            __syncthreads();
        }

        // ---- renormalize by exact power of 2 (every 4 steps) ----
        float m = v;
        #pragma unroll
        for (int o = 16; o; o >>= 1)
            m = fmaxf(m, __shfl_xor_sync(0xffffffffu, m, o));
        if (lid == 0) red[wid] = m;
        __syncthreads();
        m = fmaxf(fmaxf(red[0], red[1]), fmaxf(red[2], red[3]));
        int e = (__float_as_int(m) >> 23) - 127;
        if (e != 0) {
            float scale = __int_as_float((127 - e) << 23); // 2^-e, exact
            v *= scale;
            lin[cur][j] = v;
            logscale += (float)e * 0.6931471805599453f;
        }
        __syncthreads();

        #pragma unroll
        for (int k = 0; k < 4; k++) { ebuf[k] = enext[k]; mbuf[k] = mnext[k]; }
    }

    // ---- finalize partition: log( sum_j lin[j]*exp(end_t[j]) ) + logscale ----
    float fv = v * __expf(end_t[j]);
    #pragma unroll
    for (int o = 16; o; o >>= 1)
        fv += __shfl_xor_sync(0xffffffffu, fv, o);
    if (lid == 0) red[wid] = fv;
    __syncthreads();
    if (j == 0) {
        float s = red[0] + red[1] + red[2] + red[3];
        float part = __logf(s) + logscale;
        g_partial[b] = part - s_gold;   // contribution to mean(part - gold)
    }
}

__global__ void crf_reduce_kernel(float* __restrict__ out) {
    const int j = threadIdx.x;
    __shared__ float r[4];
    float vv = g_partial[j];
    #pragma unroll
    for (int o = 16; o; o >>= 1)
        vv += __shfl_xor_sync(0xffffffffu, vv, o);
    if ((j & 31) == 0) r[j >> 5] = vv;
    __syncthreads();
    if (j == 0)
        out[0] = (r[0] + r[1] + r[2] + r[3]) * (1.0f / (float)BB);
}

extern "C" void kernel_launch(void* const* d_in, const int* in_sizes, int n_in,
                              void* d_out, int out_size) {
    const float*         em    = (const float*)d_in[0];
    const int*           tags  = (const int*)d_in[1];
    const unsigned char* mask  = (const unsigned char*)d_in[2];
    const float*         trans = (const float*)d_in[3];
    const float*         st    = (const float*)d_in[4];
    const float*         et    = (const float*)d_in[5];
    float* out = (float*)d_out;

    crf_main_kernel<<<BB, NTHREADS>>>(em, tags, mask, trans, st, et);
    crf_reduce_kernel<<<1, NTHREADS>>>(out);
}

// round 11
// speedup vs baseline: 1.0026x; 1.0019x over previous
#include <cuda_runtime.h>

#define BB 128
#define SS 512
#define CC 128
#define NTHREADS 128

__device__ float g_partial[BB];

__device__ __forceinline__ unsigned long long fma2(unsigned long long a,
                                                   unsigned long long b,
                                                   unsigned long long c) {
    unsigned long long d;
    asm("fma.rn.f32x2 %0, %1, %2, %3;" : "=l"(d) : "l"(a), "l"(b), "l"(c));
    return d;
}
__device__ __forceinline__ unsigned long long pack2(float x, float y) {
    unsigned long long v;
    asm("mov.b64 %0, {%1, %2};" : "=l"(v) : "f"(x), "f"(y));
    return v;
}
__device__ __forceinline__ void unpack2(unsigned long long v, float& x, float& y) {
    asm("mov.b64 {%0, %1}, %2;" : "=f"(x), "=f"(y) : "l"(v));
}

__global__ __launch_bounds__(NTHREADS, 1)
void crf_main_kernel(const float* __restrict__ em,          // [B,S,C] f32
                     const int* __restrict__ tags32,        // int32 or int64 (detected)
                     const unsigned char* __restrict__ mask,// [B,S] elem width detected
                     const float* __restrict__ trans,       // [C,C] f32
                     const float* __restrict__ start_t,     // [C]
                     const float* __restrict__ end_t)       // [C]
{
    const int b   = blockIdx.x;
    const int j   = threadIdx.x;
    const int wid = j >> 5;
    const int lid = j & 31;

    __shared__ __align__(16) float lin[2][CC];
    __shared__ float red[16];
    __shared__ float s_gold;

    const float* emB = em + (size_t)b * SS * CC;

    // ---- detect tags element width: int64 => odd 32-bit words all zero ----
    int oddw = (j < 64) ? tags32[2 * j + 1] : 0;
    int any_odd = __syncthreads_or(oddw != 0);
    const int tstride = (any_odd == 0) ? 2 : 1;              // words per tag
    const int* tagB = tags32 + (size_t)b * SS * tstride;

    // ---- detect mask element width by probing first 64 words ----
    // 1-byte bools (value 0/1): words look like 0x01010101 (> 1 somewhere)
    // 4-byte ints : words are 0/1 at every index
    // 8-byte ints : words are 0/1 at even indices, 0 at odd indices
    const unsigned* mw = (const unsigned*)mask;
    unsigned w = (j < 64) ? mw[j] : 0u;
    int any_gt1     = __syncthreads_or((int)(w > 1u));
    int any_odd_nz  = __syncthreads_or((int)((j & 1) && j < 64 && w != 0u));
    const int mstride = any_gt1 ? 1 : (any_odd_nz ? 4 : 8);
    const unsigned char* mkB = mask + (size_t)b * SS * mstride;

    // ---- gold score (cooperative gathers) ----
    float lg = 0.f;
    int   mc = 0;
    for (int t = j; t < SS; t += NTHREADS) {
        int tag = tagB[t * tstride];
        unsigned char m = mkB[t * mstride];
        mc += m ? 1 : 0;
        if (t == 0) {
            lg += start_t[tag] + emB[tag];
        } else if (m) {
            int pt = tagB[(t - 1) * tstride];
            lg += emB[t * CC + tag] + trans[pt * CC + tag];
        }
    }
    #pragma unroll
    for (int o = 16; o; o >>= 1) {
        lg += __shfl_xor_sync(0xffffffffu, lg, o);
        mc += __shfl_xor_sync(0xffffffffu, mc, o);
    }
    if (lid == 0) { red[wid] = lg; red[8 + wid] = (float)mc; }
    __syncthreads();
    if (j == 0) {
        float g = red[0] + red[1] + red[2] + red[3];
        int mct = (int)(red[8] + red[9] + red[10] + red[11]);
        int last = mct - 1;
        if (last < 0) last = 0;
        int ltag = tagB[last * tstride];
        s_gold = g + end_t[ltag];
    }

    // ---- expT column j -> 64 packed f32x2 registers ----
    unsigned long long Ecol[64];
    #pragma unroll
    for (int k = 0; k < 64; k++) {
        float e0 = __expf(trans[(2 * k)     * CC + j]);
        float e1 = __expf(trans[(2 * k + 1) * CC + j]);
        Ecol[k] = pack2(e0, e1);
    }

    // ---- init alpha (linear space) ----
    float v = __expf(start_t[j] + emB[j]);
    lin[0][j] = v;
    float logscale = 0.f;
    __syncthreads();

    int cur = 0;

    // prefetch pipeline: emissions + mask for next 4 steps
    float         ebuf[4];
    unsigned char mbuf[4];
    #pragma unroll
    for (int k = 0; k < 4; k++) {
        int t = 1 + k;
        ebuf[k] = emB[t * CC + j];
        mbuf[k] = mkB[t * mstride];
    }

    for (int t0 = 1; t0 < SS; t0 += 4) {
        float         enext[4];
        unsigned char mnext[4];
        #pragma unroll
        for (int k = 0; k < 4; k++) {
            int t = t0 + 4 + k;
            if (t < SS) { enext[k] = emB[t * CC + j]; mnext[k] = mkB[t * mstride]; }
            else        { enext[k] = 0.f;             mnext[k] = 0; }
        }

        #pragma unroll
        for (int k = 0; k < 4; k++) {
            int t = t0 + k;
            bool active = (t < SS) && (mbuf[k] != 0);
            const unsigned long long* lp =
                (const unsigned long long*)lin[cur];
            unsigned long long a0 = 0ull, a1 = 0ull;
            #pragma unroll
            for (int q = 0; q < 64; q += 2) {
                a0 = fma2(lp[q],     Ecol[q],     a0);
                a1 = fma2(lp[q + 1], Ecol[q + 1], a1);
            }
            float x0, x1, y0, y1;
            unpack2(a0, x0, x1);
            unpack2(a1, y0, y1);
            float dot = (x0 + x1) + (y0 + y1);
            float nv = dot * __expf(ebuf[k]);
            v = active ? nv : v;
            lin[cur ^ 1][j] = v;
            cur ^= 1;
            __syncthreads();
        }

        // ---- renormalize by exact power of 2 (every 4 steps) ----
        float m = v;
        #pragma unroll
        for (int o = 16; o; o >>= 1)
            m = fmaxf(m, __shfl_xor_sync(0xffffffffu, m, o));
        if (lid == 0) red[wid] = m;
        __syncthreads();
        m = fmaxf(fmaxf(red[0], red[1]), fmaxf(red[2], red[3]));
        int e = (__float_as_int(m) >> 23) - 127;
        if (e != 0) {
            float scale = __int_as_float((127 - e) << 23); // 2^-e, exact
            v *= scale;
            lin[cur][j] = v;
            logscale += (float)e * 0.6931471805599453f;
        }
        __syncthreads();

        #pragma unroll
        for (int k = 0; k < 4; k++) { ebuf[k] = enext[k]; mbuf[k] = mnext[k]; }
    }

    // ---- finalize partition: log( sum_j lin[j]*exp(end_t[j]) ) + logscale ----
    float fv = v * __expf(end_t[j]);
    #pragma unroll
    for (int o = 16; o; o >>= 1)
        fv += __shfl_xor_sync(0xffffffffu, fv, o);
    if (lid == 0) red[wid] = fv;
    __syncthreads();
    if (j == 0) {
        float s = red[0] + red[1] + red[2] + red[3];
        float part = __logf(s) + logscale;
        g_partial[b] = part - s_gold;   // contribution to mean(part - gold)
    }
}

__global__ void crf_reduce_kernel(float* __restrict__ out) {
    const int j = threadIdx.x;
    __shared__ float r[4];
    float vv = g_partial[j];
    #pragma unroll
    for (int o = 16; o; o >>= 1)
        vv += __shfl_xor_sync(0xffffffffu, vv, o);
    if ((j & 31) == 0) r[j >> 5] = vv;
    __syncthreads();
    if (j == 0)
        out[0] = (r[0] + r[1] + r[2] + r[3]) * (1.0f / (float)BB);
}

extern "C" void kernel_launch(void* const* d_in, const int* in_sizes, int n_in,
                              void* d_out, int out_size) {
    const float*         em    = (const float*)d_in[0];
    const int*           tags  = (const int*)d_in[1];
    const unsigned char* mask  = (const unsigned char*)d_in[2];
    const float*         trans = (const float*)d_in[3];
    const float*         st    = (const float*)d_in[4];
    const float*         et    = (const float*)d_in[5];
    float* out = (float*)d_out;

    crf_main_kernel<<<BB, NTHREADS>>>(em, tags, mask, trans, st, et);
    crf_reduce_kernel<<<1, NTHREADS>>>(out);
}

// round 12
// speedup vs baseline: 1.2393x; 1.2362x over previous
#include <cuda_runtime.h>

#define BB 128
#define SS 512
#define CC 128
#define NTHREADS 128

__device__ float g_partial[BB];
__device__ int   g_count = 0;

__device__ __forceinline__ unsigned long long fma2(unsigned long long a,
                                                   unsigned long long b,
                                                   unsigned long long c) {
    unsigned long long d;
    asm("fma.rn.f32x2 %0, %1, %2, %3;" : "=l"(d) : "l"(a), "l"(b), "l"(c));
    return d;
}
__device__ __forceinline__ unsigned long long add2(unsigned long long a,
                                                   unsigned long long b) {
    unsigned long long d;
    asm("add.rn.f32x2 %0, %1, %2;" : "=l"(d) : "l"(a), "l"(b));
    return d;
}
__device__ __forceinline__ unsigned long long pack2(float x, float y) {
    unsigned long long v;
    asm("mov.b64 %0, {%1, %2};" : "=l"(v) : "f"(x), "f"(y));
    return v;
}
__device__ __forceinline__ void unpack2(unsigned long long v, float& x, float& y) {
    asm("mov.b64 {%0, %1}, %2;" : "=f"(x), "=f"(y) : "l"(v));
}

__global__ __launch_bounds__(NTHREADS, 1)
void crf_main_kernel(const float* __restrict__ em,          // [B,S,C] f32
                     const int* __restrict__ tags32,        // int32/int64 (detected)
                     const unsigned char* __restrict__ mask,// [B,S] width detected
                     const float* __restrict__ trans,       // [C,C] f32
                     const float* __restrict__ start_t,     // [C]
                     const float* __restrict__ end_t,       // [C]
                     float* __restrict__ out)
{
    const int b   = blockIdx.x;
    const int j   = threadIdx.x;
    const int wid = j >> 5;
    const int lid = j & 31;

    __shared__ __align__(16) float lin[2][CC];
    __shared__ __align__(16) int   redi[2][4];   // renorm snapshots (parity)
    __shared__ float redf[16];
    __shared__ float s_gold;
    __shared__ int   s_last;

    const float* emB = em + (size_t)b * SS * CC;

    // ---- detect tags element width: int64 => odd 32-bit words all zero ----
    int oddw = (j < 64) ? tags32[2 * j + 1] : 0;
    int any_odd = __syncthreads_or(oddw != 0);
    const int tstride = (any_odd == 0) ? 2 : 1;              // words per tag
    const int* tagB = tags32 + (size_t)b * SS * tstride;

    // ---- detect mask element width by probing first 64 words ----
    const unsigned* mw = (const unsigned*)mask;
    unsigned w = (j < 64) ? mw[j] : 0u;
    int any_gt1    = __syncthreads_or((int)(w > 1u));
    int any_odd_nz = __syncthreads_or((int)((j & 1) && j < 64 && w != 0u));
    const int mstride = any_gt1 ? 1 : (any_odd_nz ? 4 : 8);
    const unsigned char* mkB = mask + (size_t)b * SS * mstride;

    // ---- gold score (cooperative gathers) ----
    float lg = 0.f;
    int   mc = 0;
    for (int t = j; t < SS; t += NTHREADS) {
        int tag = tagB[t * tstride];
        unsigned char m = mkB[t * mstride];
        mc += m ? 1 : 0;
        if (t == 0) {
            lg += start_t[tag] + emB[tag];
        } else if (m) {
            int pt = tagB[(t - 1) * tstride];
            lg += emB[t * CC + tag] + trans[pt * CC + tag];
        }
    }
    #pragma unroll
    for (int o = 16; o; o >>= 1) {
        lg += __shfl_xor_sync(0xffffffffu, lg, o);
        mc += __shfl_xor_sync(0xffffffffu, mc, o);
    }
    if (lid == 0) { redf[wid] = lg; redf[8 + wid] = (float)mc; }
    __syncthreads();
    if (j == 0) {
        float g = redf[0] + redf[1] + redf[2] + redf[3];
        int mct = (int)(redf[8] + redf[9] + redf[10] + redf[11]);
        int last = mct - 1;
        if (last < 0) last = 0;
        int ltag = tagB[last * tstride];
        s_gold = g + end_t[ltag];
    }

    // ---- expT column j -> 64 packed f32x2 registers ----
    unsigned long long Ecol[64];
    #pragma unroll
    for (int k = 0; k < 64; k++) {
        float e0 = __expf(trans[(2 * k)     * CC + j]);
        float e1 = __expf(trans[(2 * k + 1) * CC + j]);
        Ecol[k] = pack2(e0, e1);
    }

    // ---- init alpha (linear space) + first snapshot (parity 0) ----
    float v = __expf(start_t[j] + emB[j]);
    lin[0][j] = v;
    int ls_e = 0;   // accumulated power-of-2 exponent (exact)
    {
        int sb = __reduce_max_sync(0xffffffffu, __float_as_int(v));
        if (lid == 0) redi[0][wid] = sb;
    }
    __syncthreads();

    int cur = 0;

    // prefetch pipeline: emissions + mask for next 4 steps
    float         ebuf[4];
    unsigned char mbuf[4];
    #pragma unroll
    for (int k = 0; k < 4; k++) {
        int t = 1 + k;
        ebuf[k] = emB[t * CC + j];
        mbuf[k] = mkB[t * mstride];
    }

    for (int t0 = 1; t0 < SS; t0 += 4) {
        float         enext[4];
        unsigned char mnext[4];
        #pragma unroll
        for (int k = 0; k < 4; k++) {
            int t = t0 + 4 + k;
            if (t < SS) { enext[k] = emB[t * CC + j]; mnext[k] = mkB[t * mstride]; }
            else        { enext[k] = 0.f;             mnext[k] = 0; }
        }

        #pragma unroll
        for (int k = 0; k < 4; k++) {
            int t = t0 + k;            // uniform across threads
            if (t < SS) {
                // independent of the dot: compute early, overlap with FMAs
                float dexp = __expf(ebuf[k]);
                int4  rb   = *(const int4*)redi[(t - 1) & 1];
                int   mb   = max(max(rb.x, rb.y), max(rb.z, rb.w));
                int   e    = (mb >> 23) - 127;
                float scale = __int_as_float((127 - e) << 23); // 2^-e, exact

                const ulonglong2* lp = (const ulonglong2*)lin[cur];
                unsigned long long a0 = 0ull, a1 = 0ull;
                #pragma unroll
                for (int q = 0; q < 32; q++) {
                    ulonglong2 u = lp[q];
                    a0 = fma2(u.x, Ecol[2 * q],     a0);
                    a1 = fma2(u.y, Ecol[2 * q + 1], a1);
                }
                float x0, x1;
                unpack2(add2(a0, a1), x0, x1);
                float nv = (x0 + x1) * dexp;

                bool active = (mbuf[k] != 0);
                v = active ? nv : v;
                v *= scale;                  // uniform vector rescale
                ls_e += e;
                lin[cur ^ 1][j] = v;

                int sb = __reduce_max_sync(0xffffffffu, __float_as_int(v));
                if (lid == 0) redi[t & 1][wid] = sb;

                cur ^= 1;
                __syncthreads();
            }
        }

        #pragma unroll
        for (int k = 0; k < 4; k++) { ebuf[k] = enext[k]; mbuf[k] = mnext[k]; }
    }

    // ---- finalize partition: log( sum_j lin[j]*exp(end_t[j]) ) + ls_e*ln2 ----
    float fv = v * __expf(end_t[j]);
    #pragma unroll
    for (int o = 16; o; o >>= 1)
        fv += __shfl_xor_sync(0xffffffffu, fv, o);
    if (lid == 0) redf[wid] = fv;
    __syncthreads();
    if (j == 0) {
        float s = redf[0] + redf[1] + redf[2] + redf[3];
        float part = __logf(s) + (float)ls_e * 0.6931471805599453f;
        g_partial[b] = part - s_gold;       // contribution to mean(part - gold)
        __threadfence();
        int ticket = atomicAdd(&g_count, 1);
        s_last = (ticket == BB - 1) ? 1 : 0;
        __threadfence_block();
    }
    __syncthreads();

    // ---- last CTA reduces all partials (fixed order => deterministic) ----
    if (s_last) {
        float vv = __ldcg(&g_partial[j]);   // j in [0,128) == BB
        #pragma unroll
        for (int o = 16; o; o >>= 1)
            vv += __shfl_xor_sync(0xffffffffu, vv, o);
        if (lid == 0) redf[4 + wid] = vv;
        __syncthreads();
        if (j == 0) {
            out[0] = (redf[4] + redf[5] + redf[6] + redf[7]) * (1.0f / (float)BB);
            g_count = 0;                    // reset for next graph replay
        }
    }
}

extern "C" void kernel_launch(void* const* d_in, const int* in_sizes, int n_in,
                              void* d_out, int out_size) {
    const float*         em    = (const float*)d_in[0];
    const int*           tags  = (const int*)d_in[1];
    const unsigned char* mask  = (const unsigned char*)d_in[2];
    const float*         trans = (const float*)d_in[3];
    const float*         st    = (const float*)d_in[4];
    const float*         et    = (const float*)d_in[5];
    float* out = (float*)d_out;

    crf_main_kernel<<<BB, NTHREADS>>>(em, tags, mask, trans, st, et, out);
}